// round 4
// baseline (speedup 1.0000x reference)
#include <cuda_runtime.h>
#include <math.h>

#define N_NODES 2000
#define N_EDGES 40000
#define NBT     128      // B * Tp = 4 * 32
#define C       32

// ---- scratch (no allocations allowed; __device__ globals) ----
__device__ float g_hw[(size_t)NBT * N_NODES * C];   // 32 MB
__device__ float g_deg[N_NODES];
__device__ float g_dis[N_NODES];
__device__ float g_invdeg[N_NODES];
__device__ int   g_cnt[N_NODES];
__device__ int   g_off[N_NODES + 1];
__device__ int   g_cur[N_NODES];
__device__ int   g_src[N_EDGES];
__device__ float g_nrm[N_EDGES];
__device__ int   g_anynz;      // 0 => edge_index stored as int64; !=0 => int32

// ---- edge_index accessors (layout decided by g_anynz flag) ----
__device__ __forceinline__ int edge_row(const void* ei, int e, int is64) {
    return is64 ? (int)((const long long*)ei)[e] : ((const int*)ei)[e];
}
__device__ __forceinline__ int edge_col(const void* ei, int e, int is64) {
    return is64 ? (int)((const long long*)ei)[N_EDGES + e]
                : ((const int*)ei)[N_EDGES + e];
}

// ------------------------------------------------------------------
__global__ void k_init() {
    int i = blockIdx.x * blockDim.x + threadIdx.x;
    if (i == 0) g_anynz = 0;
    if (i < N_NODES) { g_deg[i] = 1.0f; g_cnt[i] = 0; }  // self-loop weight 1
}

// Detect int64 vs int32 layout. Reads only the first 80000 int32 words,
// which is in-bounds for BOTH layouts. For int64 data (values in [0,2000)),
// every odd word is a zero high-word; for int32 data the odd words are real
// node ids (OR over 40000 random ids in [0,2000) is nonzero w.p. ~1).
__global__ void k_detect(const void* __restrict__ ei) {
    int e = blockIdx.x * blockDim.x + threadIdx.x;
    if (e < N_EDGES) {
        int hi = ((const int*)ei)[2 * e + 1];
        if (hi != 0) atomicOr(&g_anynz, 1);
    }
}

__global__ void k_deg(const void* __restrict__ ei, const float* __restrict__ ew) {
    int e = blockIdx.x * blockDim.x + threadIdx.x;
    if (e < N_EDGES) {
        int is64 = (g_anynz == 0);
        int c = edge_col(ei, e, is64);
        if ((unsigned)c < N_NODES) {
            atomicAdd(&g_deg[c], ew[e]);
            atomicAdd(&g_cnt[c], 1);
        }
    }
}

// single block, 256 threads: dis/invdeg + exclusive scan of counts -> CSR offsets
__global__ void k_scan() {
    __shared__ int sc[2048];
    __shared__ int csum[64];
    int tid = threadIdx.x;
    for (int i = tid; i < 2048; i += 256) sc[i] = (i < N_NODES) ? g_cnt[i] : 0;
    for (int i = tid; i < N_NODES; i += 256) {
        float d = g_deg[i];               // >= 1 always (self loop)
        g_dis[i]    = rsqrtf(d);
        g_invdeg[i] = 1.0f / d;           // self-loop norm = dis*dis
    }
    __syncthreads();
    if (tid < 64) {                        // per-chunk exclusive scan (32 each)
        int base = tid * 32, run = 0;
        #pragma unroll
        for (int j = 0; j < 32; j++) { int v = sc[base + j]; sc[base + j] = run; run += v; }
        csum[tid] = run;
    }
    __syncthreads();
    if (tid == 0) {
        int run = 0;
        for (int c = 0; c < 64; c++) { int v = csum[c]; csum[c] = run; run += v; }
        g_off[N_NODES] = run;
    }
    __syncthreads();
    for (int i = tid; i < N_NODES; i += 256) {
        int o = sc[i] + csum[i >> 5];
        g_off[i] = o;
        g_cur[i] = o;
    }
}

__global__ void k_fill(const void* __restrict__ ei, const float* __restrict__ ew) {
    int e = blockIdx.x * blockDim.x + threadIdx.x;
    if (e < N_EDGES) {
        int is64 = (g_anynz == 0);
        int r = edge_row(ei, e, is64);
        int c = edge_col(ei, e, is64);
        if ((unsigned)r < N_NODES && (unsigned)c < N_NODES) {
            int p = atomicAdd(&g_cur[c], 1);
            if ((unsigned)p < N_EDGES) {
                g_src[p] = r;
                g_nrm[p] = g_dis[r] * ew[e] * g_dis[c];
            }
        }
    }
}

// ------------------------------------------------------------------
// Fused gated temporal conv + GCN weight matmul.
// Block: 256 threads, tile = 128 rows (nodes) x 32 cols, one bt per blockIdx.y.
// Thread computes 2 rows x 8 cols with register accumulators; weights read as
// float4 from shared (k-major, conflict-free), x from padded shared.
__global__ void k_conv(const float* __restrict__ x,
                       const float* __restrict__ w1, const float* __restrict__ b1,
                       const float* __restrict__ w2, const float* __restrict__ b2,
                       const float* __restrict__ gw) {
    extern __shared__ float sm[];
    float* xs0 = sm;                    // 128*33
    float* xs2 = sm + 128 * 33;         // 128*33
    float* w1a = xs2 + 128 * 33;        // [k][o], 1024 each
    float* w1b = w1a + 1024;
    float* w2a = w1b + 1024;
    float* w2b = w2a + 1024;
    float* gws = w2b + 1024;            // gcn_w [d][e]
    __shared__ float bs1[32], bs2[32];

    int bt = blockIdx.y;
    int b = bt >> 5, t = bt & 31;
    int n0 = blockIdx.x * 128;
    int nrows = N_NODES - n0; if (nrows > 128) nrows = 128;
    int tid = threadIdx.x;

    for (int i = tid; i < 1024; i += 256) {
        int o = i & 31, cc = i >> 5;
        w1a[cc * 32 + o] = w1[o * 64 + cc * 2 + 0];
        w1b[cc * 32 + o] = w1[o * 64 + cc * 2 + 1];
        w2a[cc * 32 + o] = w2[o * 64 + cc * 2 + 0];
        w2b[cc * 32 + o] = w2[o * 64 + cc * 2 + 1];
        gws[i] = gw[i];
    }
    if (tid < 32) { bs1[tid] = b1[tid]; bs2[tid] = b2[tid]; }

    const float* x0p = x + ((size_t)(b * 34 + t)     * N_NODES + n0) * C;
    const float* x2p = x + ((size_t)(b * 34 + t + 2) * N_NODES + n0) * C;
    int nelem = nrows * 32;
    for (int i = tid; i < nelem; i += 256) {
        int r = i >> 5, cc = i & 31;
        xs0[r * 33 + cc] = x0p[i];
        xs2[r * 33 + cc] = x2p[i];
    }
    __syncthreads();

    int cg = tid & 3;          // column group (8 cols each)
    int rt = tid >> 2;         // 0..63
    int r0 = rt * 2, r1 = r0 + 1;
    int co = cg * 8;

    float a1[2][8], a2[2][8];
    #pragma unroll
    for (int j = 0; j < 8; j++) {
        float v1 = bs1[co + j], v2 = bs2[co + j];
        a1[0][j] = v1; a1[1][j] = v1;
        a2[0][j] = v2; a2[1][j] = v2;
    }

    #pragma unroll 8
    for (int k = 0; k < 32; k++) {
        float xa0 = xs0[r0 * 33 + k], xa1 = xs0[r1 * 33 + k];
        float xb0 = xs2[r0 * 33 + k], xb1 = xs2[r1 * 33 + k];
        float4 t0, t1;
        // gate1
        t0 = *(const float4*)&w1a[k * 32 + co];
        t1 = *(const float4*)&w1a[k * 32 + co + 4];
        float wv[8] = {t0.x, t0.y, t0.z, t0.w, t1.x, t1.y, t1.z, t1.w};
        t0 = *(const float4*)&w1b[k * 32 + co];
        t1 = *(const float4*)&w1b[k * 32 + co + 4];
        float uv[8] = {t0.x, t0.y, t0.z, t0.w, t1.x, t1.y, t1.z, t1.w};
        #pragma unroll
        for (int j = 0; j < 8; j++) {
            a1[0][j] += xa0 * wv[j] + xb0 * uv[j];
            a1[1][j] += xa1 * wv[j] + xb1 * uv[j];
        }
        // gate2
        t0 = *(const float4*)&w2a[k * 32 + co];
        t1 = *(const float4*)&w2a[k * 32 + co + 4];
        float wv2[8] = {t0.x, t0.y, t0.z, t0.w, t1.x, t1.y, t1.z, t1.w};
        t0 = *(const float4*)&w2b[k * 32 + co];
        t1 = *(const float4*)&w2b[k * 32 + co + 4];
        float uv2[8] = {t0.x, t0.y, t0.z, t0.w, t1.x, t1.y, t1.z, t1.w};
        #pragma unroll
        for (int j = 0; j < 8; j++) {
            a2[0][j] += xa0 * wv2[j] + xb0 * uv2[j];
            a2[1][j] += xa1 * wv2[j] + xb1 * uv2[j];
        }
    }

    // g = tanh(a1) * sigmoid(a2)
    float g[2][8];
    #pragma unroll
    for (int i2 = 0; i2 < 2; i2++)
        #pragma unroll
        for (int j = 0; j < 8; j++) {
            float th = tanhf(a1[i2][j]);
            float sg = 1.0f / (1.0f + __expf(-a2[i2][j]));
            g[i2][j] = th * sg;
        }

    __syncthreads();                     // all xs0 reads done; reuse as g-tile
    #pragma unroll
    for (int j = 0; j < 8; j++) {
        xs0[r0 * 33 + co + j] = g[0][j];
        xs0[r1 * 33 + co + j] = g[1][j];
    }
    __syncthreads();

    float h[2][8];
    #pragma unroll
    for (int i2 = 0; i2 < 2; i2++)
        #pragma unroll
        for (int j = 0; j < 8; j++) h[i2][j] = 0.0f;

    #pragma unroll 8
    for (int k = 0; k < 32; k++) {
        float g0 = xs0[r0 * 33 + k], g1v = xs0[r1 * 33 + k];
        float4 t0 = *(const float4*)&gws[k * 32 + co];
        float4 t1 = *(const float4*)&gws[k * 32 + co + 4];
        float wv[8] = {t0.x, t0.y, t0.z, t0.w, t1.x, t1.y, t1.z, t1.w};
        #pragma unroll
        for (int j = 0; j < 8; j++) {
            h[0][j] += g0  * wv[j];
            h[1][j] += g1v * wv[j];
        }
    }

    float* outp = g_hw + ((size_t)bt * N_NODES + n0) * C;
    if (r0 < nrows) {
        *(float4*)&outp[r0 * 32 + co]     = make_float4(h[0][0], h[0][1], h[0][2], h[0][3]);
        *(float4*)&outp[r0 * 32 + co + 4] = make_float4(h[0][4], h[0][5], h[0][6], h[0][7]);
    }
    if (r1 < nrows) {
        *(float4*)&outp[r1 * 32 + co]     = make_float4(h[1][0], h[1][1], h[1][2], h[1][3]);
        *(float4*)&outp[r1 * 32 + co + 4] = make_float4(h[1][4], h[1][5], h[1][6], h[1][7]);
    }
}

// ------------------------------------------------------------------
// Gather: warp per (bt, dst), lane = channel. hw slice per bt (256KB) is L2-resident.
__global__ void k_gather(const float* __restrict__ gb, float* __restrict__ out) {
    int w = (blockIdx.x * blockDim.x + threadIdx.x) >> 5;
    int lane = threadIdx.x & 31;
    if (w >= NBT * N_NODES) return;
    int bt  = w / N_NODES;
    int dst = w - bt * N_NODES;
    const float* hb = g_hw + (size_t)bt * N_NODES * C;

    float acc  = gb[lane] + g_invdeg[dst] * hb[dst * 32 + lane];
    float acc2 = 0.0f;
    int s = g_off[dst], e = g_off[dst + 1];
    int i = s;
    for (; i + 1 < e; i += 2) {
        int   s0 = g_src[i],  s1 = g_src[i + 1];
        float v0 = g_nrm[i],  v1 = g_nrm[i + 1];
        acc  += v0 * hb[s0 * 32 + lane];
        acc2 += v1 * hb[s1 * 32 + lane];
    }
    if (i < e) acc += g_nrm[i] * hb[g_src[i] * 32 + lane];

    out[(size_t)w * 32 + lane] = acc + acc2;
}

// ------------------------------------------------------------------
extern "C" void kernel_launch(void* const* d_in, const int* in_sizes, int n_in,
                              void* d_out, int out_size) {
    const float* x  = (const float*)d_in[0];
    const void*  ei = d_in[1];                 // int64 OR int32 — detected on device
    const float* ew = (const float*)d_in[2];
    const float* w1 = (const float*)d_in[3];
    const float* b1 = (const float*)d_in[4];
    const float* w2 = (const float*)d_in[5];
    const float* b2 = (const float*)d_in[6];
    const float* gw = (const float*)d_in[7];
    const float* gb = (const float*)d_in[8];
    float* out = (float*)d_out;

    k_init  <<<(N_NODES + 255) / 256, 256>>>();
    k_detect<<<(N_EDGES + 255) / 256, 256>>>(ei);
    k_deg   <<<(N_EDGES + 255) / 256, 256>>>(ei, ew);
    k_scan  <<<1, 256>>>();
    k_fill  <<<(N_EDGES + 255) / 256, 256>>>(ei, ew);

    int smem = (2 * 128 * 33 + 5 * 1024) * (int)sizeof(float);   // 54272 B
    cudaFuncSetAttribute(k_conv, cudaFuncAttributeMaxDynamicSharedMemorySize, smem);
    dim3 grid(16, NBT);
    k_conv<<<grid, 256, smem>>>(x, w1, b1, w2, b2, gw);

    int totw = NBT * N_NODES;                        // 256000 warps
    k_gather<<<(totw * 32 + 255) / 256, 256>>>(gb, out);
}

// round 5
// speedup vs baseline: 1.1215x; 1.1215x over previous
#include <cuda_runtime.h>
#include <math.h>

#define N_NODES 2000
#define N_EDGES 40000
#define NBT     128      // B * Tp = 4 * 32
#define C       32

typedef unsigned long long u64;

// ---- f32x2 packed helpers (FFMA2 path: only reachable via PTX) ----
__device__ __forceinline__ u64 pack2(float lo, float hi) {
    u64 d; asm("mov.b64 %0, {%1, %2};" : "=l"(d) : "f"(lo), "f"(hi)); return d;
}
__device__ __forceinline__ void unpack2(u64 v, float& lo, float& hi) {
    asm("mov.b64 {%0, %1}, %2;" : "=f"(lo), "=f"(hi) : "l"(v));
}
__device__ __forceinline__ u64 fma2(u64 a, u64 b, u64 c) {
    u64 d; asm("fma.rn.f32x2 %0, %1, %2, %3;" : "=l"(d) : "l"(a), "l"(b), "l"(c)); return d;
}

// ---- scratch (no allocations allowed; __device__ globals) ----
__device__ float g_hw[(size_t)NBT * N_NODES * C];   // 32 MB
__device__ float g_deg[N_NODES];
__device__ float g_dis[N_NODES];
__device__ float g_invdeg[N_NODES];
__device__ int   g_cnt[N_NODES];
__device__ int   g_off[N_NODES + 1];
__device__ int   g_cur[N_NODES];
__device__ int   g_src[N_EDGES];
__device__ float g_nrm[N_EDGES];
__device__ int   g_anynz = 0;  // 0 => edge_index int64; !=0 => int32. Reset by k_gather tail.

// ---- edge_index accessors (layout decided by g_anynz flag) ----
__device__ __forceinline__ int edge_row(const void* ei, int e, int is64) {
    return is64 ? (int)((const long long*)ei)[e] : ((const int*)ei)[e];
}
__device__ __forceinline__ int edge_col(const void* ei, int e, int is64) {
    return is64 ? (int)((const long long*)ei)[N_EDGES + e]
                : ((const int*)ei)[N_EDGES + e];
}

// ------------------------------------------------------------------
// Fused: init deg/cnt (i < N_NODES) + int64/int32 layout detect (i < N_EDGES).
// g_anynz is 0 on entry (static init on first call; reset by k_gather after).
__global__ void k_initdetect(const void* __restrict__ ei) {
    int i = blockIdx.x * blockDim.x + threadIdx.x;
    if (i < N_NODES) { g_deg[i] = 1.0f; g_cnt[i] = 0; }  // self-loop weight 1
    if (i < N_EDGES) {
        int hi = ((const int*)ei)[2 * i + 1];   // in-bounds for BOTH layouts
        if (hi != 0) atomicOr(&g_anynz, 1);
    }
}

__global__ void k_deg(const void* __restrict__ ei, const float* __restrict__ ew) {
    int e = blockIdx.x * blockDim.x + threadIdx.x;
    if (e < N_EDGES) {
        int is64 = (g_anynz == 0);
        int c = edge_col(ei, e, is64);
        if ((unsigned)c < N_NODES) {
            atomicAdd(&g_deg[c], ew[e]);
            atomicAdd(&g_cnt[c], 1);
        }
    }
}

// single block, 256 threads: shfl-hierarchical exclusive scan + dis/invdeg.
__global__ void k_scan() {
    __shared__ int wsum[8];
    int tid = threadIdx.x;
    int lane = tid & 31, wid = tid >> 5;

    int base = tid * 8;               // 256*8 = 2048 >= N_NODES
    int v[8];
    int tot = 0;
    #pragma unroll
    for (int j = 0; j < 8; j++) {
        int idx = base + j;
        int c = (idx < N_NODES) ? g_cnt[idx] : 0;
        v[j] = tot;                   // local exclusive prefix
        tot += c;
    }
    int incl = tot;
    #pragma unroll
    for (int d = 1; d < 32; d <<= 1) {
        int n = __shfl_up_sync(0xffffffffu, incl, d);
        if (lane >= d) incl += n;
    }
    if (lane == 31) wsum[wid] = incl;
    int texcl = incl - tot;
    __syncthreads();
    if (tid == 0) {
        int run = 0;
        #pragma unroll
        for (int w = 0; w < 8; w++) { int t = wsum[w]; wsum[w] = run; run += t; }
        g_off[N_NODES] = run;
    }
    __syncthreads();
    int off = wsum[wid] + texcl;
    #pragma unroll
    for (int j = 0; j < 8; j++) {
        int idx = base + j;
        if (idx < N_NODES) { int o = off + v[j]; g_off[idx] = o; g_cur[idx] = o; }
    }
    for (int i = tid; i < N_NODES; i += 256) {
        float d = g_deg[i];               // >= 1 always (self loop)
        g_dis[i]    = rsqrtf(d);
        g_invdeg[i] = 1.0f / d;           // self-loop norm = dis*dis
    }
}

__global__ void k_fill(const void* __restrict__ ei, const float* __restrict__ ew) {
    int e = blockIdx.x * blockDim.x + threadIdx.x;
    if (e < N_EDGES) {
        int is64 = (g_anynz == 0);
        int r = edge_row(ei, e, is64);
        int c = edge_col(ei, e, is64);
        if ((unsigned)r < N_NODES && (unsigned)c < N_NODES) {
            int p = atomicAdd(&g_cur[c], 1);
            if ((unsigned)p < N_EDGES) {
                g_src[p] = r;
                g_nrm[p] = g_dis[r] * ew[e] * g_dis[c];
            }
        }
    }
}

// ------------------------------------------------------------------
// Fused gated temporal conv + GCN weight matmul, FFMA2 (f32x2) version.
// Block: 128 threads, tile = 128 rows (nodes) x 32 cols, one bt per blockIdx.y.
// Thread computes 4 rows x 8 cols; columns packed as 4 f32x2 pairs.
// Weights in shared [k][o] so 4 col-pairs load as 2x LDS.128 (broadcast).
__global__ void __launch_bounds__(128) k_conv(
                       const float* __restrict__ x,
                       const float* __restrict__ w1, const float* __restrict__ b1,
                       const float* __restrict__ w2, const float* __restrict__ b2,
                       const float* __restrict__ gw) {
    extern __shared__ float sm[];
    float* xs0 = sm;                    // 128*33
    float* xs2 = sm + 128 * 33;         // 128*33
    float* w1a = xs2 + 128 * 33;        // [k][o], 1024 each
    float* w1b = w1a + 1024;
    float* w2a = w1b + 1024;
    float* w2b = w2a + 1024;
    float* gws = w2b + 1024;            // gcn_w [d][e]
    __shared__ __align__(16) float bs1[32];
    __shared__ __align__(16) float bs2[32];

    int bt = blockIdx.y;
    int b = bt >> 5, t = bt & 31;
    int n0 = blockIdx.x * 128;
    int nrows = N_NODES - n0; if (nrows > 128) nrows = 128;
    int tid = threadIdx.x;

    for (int i = tid; i < 1024; i += 128) {
        int o = i & 31, cc = i >> 5;
        w1a[cc * 32 + o] = w1[o * 64 + cc * 2 + 0];
        w1b[cc * 32 + o] = w1[o * 64 + cc * 2 + 1];
        w2a[cc * 32 + o] = w2[o * 64 + cc * 2 + 0];
        w2b[cc * 32 + o] = w2[o * 64 + cc * 2 + 1];
        gws[i] = gw[i];
    }
    if (tid < 32) { bs1[tid] = b1[tid]; bs2[tid] = b2[tid]; }

    const float* x0p = x + ((size_t)(b * 34 + t)     * N_NODES + n0) * C;
    const float* x2p = x + ((size_t)(b * 34 + t + 2) * N_NODES + n0) * C;
    int nelem = nrows * 32;
    for (int i = tid; i < nelem; i += 128) {
        int r = i >> 5, cc = i & 31;
        xs0[r * 33 + cc] = x0p[i];
        xs2[r * 33 + cc] = x2p[i];
    }
    __syncthreads();

    int cg = tid & 3;          // column group (8 cols = 4 pairs)
    int rt = tid >> 2;         // 0..31
    int r0 = rt * 4;           // 4 rows per thread
    int co = cg * 8;

    u64 acc1[4][4], acc2[4][4];
    {
        const u64* bp1 = (const u64*)&bs1[co];
        const u64* bp2 = (const u64*)&bs2[co];
        #pragma unroll
        for (int p = 0; p < 4; p++) {
            u64 v1 = bp1[p], v2 = bp2[p];
            #pragma unroll
            for (int r = 0; r < 4; r++) { acc1[r][p] = v1; acc2[r][p] = v2; }
        }
    }

    #pragma unroll 2
    for (int k = 0; k < 32; k++) {
        u64 xa[4], xb[4];
        #pragma unroll
        for (int r = 0; r < 4; r++) {
            float v0 = xs0[(r0 + r) * 33 + k];
            float v2 = xs2[(r0 + r) * 33 + k];
            xa[r] = pack2(v0, v0);
            xb[r] = pack2(v2, v2);
        }
        const int wb = k * 32 + co;
        // gate1: acc1 += xa*w1a + xb*w1b
        {
            ulonglong2 wlo = *(const ulonglong2*)&w1a[wb];
            ulonglong2 whi = *(const ulonglong2*)&w1a[wb + 4];
            u64 wv[4] = {wlo.x, wlo.y, whi.x, whi.y};
            #pragma unroll
            for (int r = 0; r < 4; r++)
                #pragma unroll
                for (int p = 0; p < 4; p++)
                    acc1[r][p] = fma2(xa[r], wv[p], acc1[r][p]);
            wlo = *(const ulonglong2*)&w1b[wb];
            whi = *(const ulonglong2*)&w1b[wb + 4];
            u64 uv[4] = {wlo.x, wlo.y, whi.x, whi.y};
            #pragma unroll
            for (int r = 0; r < 4; r++)
                #pragma unroll
                for (int p = 0; p < 4; p++)
                    acc1[r][p] = fma2(xb[r], uv[p], acc1[r][p]);
        }
        // gate2: acc2 += xa*w2a + xb*w2b
        {
            ulonglong2 wlo = *(const ulonglong2*)&w2a[wb];
            ulonglong2 whi = *(const ulonglong2*)&w2a[wb + 4];
            u64 wv[4] = {wlo.x, wlo.y, whi.x, whi.y};
            #pragma unroll
            for (int r = 0; r < 4; r++)
                #pragma unroll
                for (int p = 0; p < 4; p++)
                    acc2[r][p] = fma2(xa[r], wv[p], acc2[r][p]);
            wlo = *(const ulonglong2*)&w2b[wb];
            whi = *(const ulonglong2*)&w2b[wb + 4];
            u64 uv[4] = {wlo.x, wlo.y, whi.x, whi.y};
            #pragma unroll
            for (int r = 0; r < 4; r++)
                #pragma unroll
                for (int p = 0; p < 4; p++)
                    acc2[r][p] = fma2(xb[r], uv[p], acc2[r][p]);
        }
    }

    __syncthreads();                 // all xs0/xs2 reads done; reuse xs0 as g-tile
    // g = tanh(a1) * sigmoid(a2);  tanh via exp-form (1 MUFU each)
    #pragma unroll
    for (int r = 0; r < 4; r++) {
        #pragma unroll
        for (int p = 0; p < 4; p++) {
            float a0, a1v, c0, c1;
            unpack2(acc1[r][p], a0, a1v);
            unpack2(acc2[r][p], c0, c1);
            float th0 = 2.0f / (1.0f + __expf(-2.0f * a0)) - 1.0f;
            float th1 = 2.0f / (1.0f + __expf(-2.0f * a1v)) - 1.0f;
            float sg0 = 1.0f / (1.0f + __expf(-c0));
            float sg1 = 1.0f / (1.0f + __expf(-c1));
            xs0[(r0 + r) * 33 + co + 2 * p]     = th0 * sg0;
            xs0[(r0 + r) * 33 + co + 2 * p + 1] = th1 * sg1;
        }
    }
    __syncthreads();

    u64 hacc[4][4];
    u64 z = pack2(0.0f, 0.0f);
    #pragma unroll
    for (int r = 0; r < 4; r++)
        #pragma unroll
        for (int p = 0; p < 4; p++) hacc[r][p] = z;

    #pragma unroll 4
    for (int k = 0; k < 32; k++) {
        u64 gp[4];
        #pragma unroll
        for (int r = 0; r < 4; r++) {
            float gv = xs0[(r0 + r) * 33 + k];
            gp[r] = pack2(gv, gv);
        }
        ulonglong2 wlo = *(const ulonglong2*)&gws[k * 32 + co];
        ulonglong2 whi = *(const ulonglong2*)&gws[k * 32 + co + 4];
        u64 wv[4] = {wlo.x, wlo.y, whi.x, whi.y};
        #pragma unroll
        for (int r = 0; r < 4; r++)
            #pragma unroll
            for (int p = 0; p < 4; p++)
                hacc[r][p] = fma2(gp[r], wv[p], hacc[r][p]);
    }

    float* outp = g_hw + ((size_t)bt * N_NODES + n0) * C;
    #pragma unroll
    for (int r = 0; r < 4; r++) {
        int row = r0 + r;
        if (row < nrows) {
            ulonglong2 lo; lo.x = hacc[r][0]; lo.y = hacc[r][1];
            ulonglong2 hi; hi.x = hacc[r][2]; hi.y = hacc[r][3];
            *(ulonglong2*)&outp[row * 32 + co]     = lo;
            *(ulonglong2*)&outp[row * 32 + co + 4] = hi;
        }
    }
}

// ------------------------------------------------------------------
// Gather: warp per (bt, dst), lane = channel; 4 accumulators for MLP.
// hw slice per bt (256KB) is L2-resident.
__global__ void k_gather(const float* __restrict__ gb, float* __restrict__ out) {
    int w = (blockIdx.x * blockDim.x + threadIdx.x) >> 5;
    int lane = threadIdx.x & 31;
    if (w < NBT * N_NODES) {
        int bt  = w / N_NODES;
        int dst = w - bt * N_NODES;
        const float* hb = g_hw + (size_t)bt * (N_NODES * C);

        float acc0 = gb[lane] + g_invdeg[dst] * hb[dst * 32 + lane];
        float acc1 = 0.0f, acc2 = 0.0f, acc3 = 0.0f;
        int s = g_off[dst], e = g_off[dst + 1];
        int i = s;
        for (; i + 3 < e; i += 4) {
            int   s0 = g_src[i],     s1 = g_src[i + 1];
            int   s2 = g_src[i + 2], s3 = g_src[i + 3];
            float n0v = g_nrm[i],     n1v = g_nrm[i + 1];
            float n2v = g_nrm[i + 2], n3v = g_nrm[i + 3];
            acc0 += n0v * hb[s0 * 32 + lane];
            acc1 += n1v * hb[s1 * 32 + lane];
            acc2 += n2v * hb[s2 * 32 + lane];
            acc3 += n3v * hb[s3 * 32 + lane];
        }
        for (; i < e; i++) acc0 += g_nrm[i] * hb[g_src[i] * 32 + lane];

        out[(size_t)w * 32 + lane] = (acc0 + acc1) + (acc2 + acc3);
    }
    // Reset detect flag for the next kernel_launch call (invariant: 0 on entry).
    if (blockIdx.x == 0 && threadIdx.x == 0) g_anynz = 0;
}

// ------------------------------------------------------------------
extern "C" void kernel_launch(void* const* d_in, const int* in_sizes, int n_in,
                              void* d_out, int out_size) {
    const float* x  = (const float*)d_in[0];
    const void*  ei = d_in[1];                 // int64 OR int32 — detected on device
    const float* ew = (const float*)d_in[2];
    const float* w1 = (const float*)d_in[3];
    const float* b1 = (const float*)d_in[4];
    const float* w2 = (const float*)d_in[5];
    const float* b2 = (const float*)d_in[6];
    const float* gw = (const float*)d_in[7];
    const float* gb = (const float*)d_in[8];
    float* out = (float*)d_out;

    k_initdetect<<<(N_EDGES + 255) / 256, 256>>>(ei);
    k_deg       <<<(N_EDGES + 255) / 256, 256>>>(ei, ew);
    k_scan      <<<1, 256>>>();
    k_fill      <<<(N_EDGES + 255) / 256, 256>>>(ei, ew);

    int smem = (2 * 128 * 33 + 5 * 1024) * (int)sizeof(float);   // 54272 B
    cudaFuncSetAttribute(k_conv, cudaFuncAttributeMaxDynamicSharedMemorySize, smem);
    dim3 grid(16, NBT);
    k_conv<<<grid, 128, smem>>>(x, w1, b1, w2, b2, gw);

    int totw = NBT * N_NODES;                        // 256000 warps
    k_gather<<<(totw * 32 + 255) / 256, 256>>>(gb, out);
}

// round 6
// speedup vs baseline: 1.2241x; 1.0915x over previous
#include <cuda_runtime.h>
#include <math.h>

#define N_NODES 2000
#define N_EDGES 40000
#define NBT     128      // B * Tp = 4 * 32
#define C       32

typedef unsigned long long u64;

// ---- f32x2 packed helpers (FFMA2 path: only reachable via PTX) ----
__device__ __forceinline__ u64 pack2(float lo, float hi) {
    u64 d; asm("mov.b64 %0, {%1, %2};" : "=l"(d) : "f"(lo), "f"(hi)); return d;
}
__device__ __forceinline__ void unpack2(u64 v, float& lo, float& hi) {
    asm("mov.b64 {%0, %1}, %2;" : "=f"(lo), "=f"(hi) : "l"(v));
}
__device__ __forceinline__ u64 fma2(u64 a, u64 b, u64 c) {
    u64 d; asm("fma.rn.f32x2 %0, %1, %2, %3;" : "=l"(d) : "l"(a), "l"(b), "l"(c)); return d;
}

// ---- scratch (no allocations; __device__ globals, zero-init at load) ----
__device__ __align__(16) float g_hw[(size_t)NBT * N_NODES * C];   // 32 MB
__device__ float g_deg[N_NODES];     // edge-weight sums; MUST be 0 on entry (scan re-zeroes)
__device__ float g_dis[N_NODES];
__device__ float g_invdeg[N_NODES];
__device__ int   g_cnt[N_NODES];     // in-degree counts; MUST be 0 on entry (scan re-zeroes)
__device__ int   g_off[N_NODES + 1];
__device__ int   g_cur[N_NODES];
__device__ int   g_src[N_EDGES];
__device__ float g_nrm[N_EDGES];

// Per-block int64-vs-int32 layout detection: OR of hi/odd words for this
// block's edges. int64 data (ids < 2000) => all zero. int32 => real ids.
__device__ __forceinline__ int detect_is64(const void* ei, int e, int valid) {
    int nz = 0;
    if (valid) {
        const int* w = (const int*)ei;
        nz = w[2 * e + 1] | w[2 * (N_EDGES + e) + 1];
    }
    return !__syncthreads_or(nz);
}
__device__ __forceinline__ int edge_row(const void* ei, int e, int is64) {
    return is64 ? (int)((const long long*)ei)[e] : ((const int*)ei)[e];
}
__device__ __forceinline__ int edge_col(const void* ei, int e, int is64) {
    return is64 ? (int)((const long long*)ei)[N_EDGES + e]
                : ((const int*)ei)[N_EDGES + e];
}

// ------------------------------------------------------------------
__global__ void k_deg(const void* __restrict__ ei, const float* __restrict__ ew) {
    int e = blockIdx.x * blockDim.x + threadIdx.x;
    int valid = (e < N_EDGES);
    int is64 = detect_is64(ei, e, valid);
    if (valid) {
        int c = edge_col(ei, e, is64);
        if ((unsigned)c < N_NODES) {
            atomicAdd(&g_deg[c], ew[e]);
            atomicAdd(&g_cnt[c], 1);
        }
    }
}

// single block, 256 threads: shfl-hierarchical exclusive scan + dis/invdeg.
// Consumes g_cnt/g_deg and re-zeroes them for the next kernel_launch call.
__global__ void k_scan() {
    __shared__ int wsum[8];
    int tid = threadIdx.x;
    int lane = tid & 31, wid = tid >> 5;

    int base = tid * 8;               // 256*8 = 2048 >= N_NODES
    int v[8];
    int tot = 0;
    #pragma unroll
    for (int j = 0; j < 8; j++) {
        int idx = base + j;
        int c = (idx < N_NODES) ? g_cnt[idx] : 0;
        v[j] = tot;                   // local exclusive prefix
        tot += c;
    }
    int incl = tot;
    #pragma unroll
    for (int d = 1; d < 32; d <<= 1) {
        int n = __shfl_up_sync(0xffffffffu, incl, d);
        if (lane >= d) incl += n;
    }
    if (lane == 31) wsum[wid] = incl;
    int texcl = incl - tot;
    __syncthreads();
    if (tid == 0) {
        int run = 0;
        #pragma unroll
        for (int w = 0; w < 8; w++) { int t = wsum[w]; wsum[w] = run; run += t; }
        g_off[N_NODES] = run;
    }
    __syncthreads();
    int off = wsum[wid] + texcl;
    #pragma unroll
    for (int j = 0; j < 8; j++) {
        int idx = base + j;
        if (idx < N_NODES) {
            int o = off + v[j];
            g_off[idx] = o; g_cur[idx] = o;
            g_cnt[idx] = 0;                    // reset for next call
        }
    }
    for (int i = tid; i < N_NODES; i += 256) {
        float d = 1.0f + g_deg[i];            // self-loop weight 1
        g_dis[i]    = rsqrtf(d);
        g_invdeg[i] = 1.0f / d;               // self-loop norm = dis*dis
        g_deg[i]    = 0.0f;                   // reset for next call
    }
}

__global__ void k_fill(const void* __restrict__ ei, const float* __restrict__ ew) {
    int e = blockIdx.x * blockDim.x + threadIdx.x;
    int valid = (e < N_EDGES);
    int is64 = detect_is64(ei, e, valid);
    if (valid) {
        int r = edge_row(ei, e, is64);
        int c = edge_col(ei, e, is64);
        if ((unsigned)r < N_NODES && (unsigned)c < N_NODES) {
            int p = atomicAdd(&g_cur[c], 1);
            if ((unsigned)p < N_EDGES) {
                g_src[p] = r;
                g_nrm[p] = g_dis[r] * ew[e] * g_dis[c];
            }
        }
    }
}

// ------------------------------------------------------------------
// Fused gated temporal conv + GCN weight matmul, FFMA2 (f32x2) version.
// Block: 128 threads, tile = 128 rows (nodes) x 32 cols, one bt per blockIdx.y.
// Thread computes 4 rows x 8 cols; columns packed as 4 f32x2 pairs.
__global__ void __launch_bounds__(128) k_conv(
                       const float* __restrict__ x,
                       const float* __restrict__ w1, const float* __restrict__ b1,
                       const float* __restrict__ w2, const float* __restrict__ b2,
                       const float* __restrict__ gw) {
    extern __shared__ float sm[];
    float* xs0 = sm;                    // 128*33
    float* xs2 = sm + 128 * 33;         // 128*33
    float* w1a = xs2 + 128 * 33;        // [k][o], 1024 each
    float* w1b = w1a + 1024;
    float* w2a = w1b + 1024;
    float* w2b = w2a + 1024;
    float* gws = w2b + 1024;            // gcn_w [d][e]
    __shared__ __align__(16) float bs1[32];
    __shared__ __align__(16) float bs2[32];

    int bt = blockIdx.y;
    int b = bt >> 5, t = bt & 31;
    int n0 = blockIdx.x * 128;
    int nrows = N_NODES - n0; if (nrows > 128) nrows = 128;
    int tid = threadIdx.x;

    for (int i = tid; i < 1024; i += 128) {
        int o = i & 31, cc = i >> 5;
        w1a[cc * 32 + o] = w1[o * 64 + cc * 2 + 0];
        w1b[cc * 32 + o] = w1[o * 64 + cc * 2 + 1];
        w2a[cc * 32 + o] = w2[o * 64 + cc * 2 + 0];
        w2b[cc * 32 + o] = w2[o * 64 + cc * 2 + 1];
        gws[i] = gw[i];
    }
    if (tid < 32) { bs1[tid] = b1[tid]; bs2[tid] = b2[tid]; }

    // Vectorized x load: LDG.128, scatter 4x STS.32 into padded (stride-33) smem.
    const float4* x0v = (const float4*)(x + ((size_t)(b * 34 + t)     * N_NODES + n0) * C);
    const float4* x2v = (const float4*)(x + ((size_t)(b * 34 + t + 2) * N_NODES + n0) * C);
    int nvec = nrows * 8;               // float4s
    for (int i = tid; i < nvec; i += 128) {
        int r = i >> 3, c4 = (i & 7) * 4;
        float4 v = x0v[i];
        float* d0 = &xs0[r * 33 + c4];
        d0[0] = v.x; d0[1] = v.y; d0[2] = v.z; d0[3] = v.w;
        float4 u = x2v[i];
        float* d2 = &xs2[r * 33 + c4];
        d2[0] = u.x; d2[1] = u.y; d2[2] = u.z; d2[3] = u.w;
    }
    __syncthreads();

    int cg = tid & 3;          // column group (8 cols = 4 pairs)
    int rt = tid >> 2;         // 0..31
    int r0 = rt * 4;           // 4 rows per thread
    int co = cg * 8;

    u64 acc1[4][4], acc2[4][4];
    {
        const u64* bp1 = (const u64*)&bs1[co];
        const u64* bp2 = (const u64*)&bs2[co];
        #pragma unroll
        for (int p = 0; p < 4; p++) {
            u64 v1 = bp1[p], v2 = bp2[p];
            #pragma unroll
            for (int r = 0; r < 4; r++) { acc1[r][p] = v1; acc2[r][p] = v2; }
        }
    }

    #pragma unroll 2
    for (int k = 0; k < 32; k++) {
        u64 xa[4], xb[4];
        #pragma unroll
        for (int r = 0; r < 4; r++) {
            float v0 = xs0[(r0 + r) * 33 + k];
            float v2 = xs2[(r0 + r) * 33 + k];
            xa[r] = pack2(v0, v0);
            xb[r] = pack2(v2, v2);
        }
        const int wb = k * 32 + co;
        {
            ulonglong2 wlo = *(const ulonglong2*)&w1a[wb];
            ulonglong2 whi = *(const ulonglong2*)&w1a[wb + 4];
            u64 wv[4] = {wlo.x, wlo.y, whi.x, whi.y};
            #pragma unroll
            for (int r = 0; r < 4; r++)
                #pragma unroll
                for (int p = 0; p < 4; p++)
                    acc1[r][p] = fma2(xa[r], wv[p], acc1[r][p]);
            wlo = *(const ulonglong2*)&w1b[wb];
            whi = *(const ulonglong2*)&w1b[wb + 4];
            u64 uv[4] = {wlo.x, wlo.y, whi.x, whi.y};
            #pragma unroll
            for (int r = 0; r < 4; r++)
                #pragma unroll
                for (int p = 0; p < 4; p++)
                    acc1[r][p] = fma2(xb[r], uv[p], acc1[r][p]);
        }
        {
            ulonglong2 wlo = *(const ulonglong2*)&w2a[wb];
            ulonglong2 whi = *(const ulonglong2*)&w2a[wb + 4];
            u64 wv[4] = {wlo.x, wlo.y, whi.x, whi.y};
            #pragma unroll
            for (int r = 0; r < 4; r++)
                #pragma unroll
                for (int p = 0; p < 4; p++)
                    acc2[r][p] = fma2(xa[r], wv[p], acc2[r][p]);
            wlo = *(const ulonglong2*)&w2b[wb];
            whi = *(const ulonglong2*)&w2b[wb + 4];
            u64 uv[4] = {wlo.x, wlo.y, whi.x, whi.y};
            #pragma unroll
            for (int r = 0; r < 4; r++)
                #pragma unroll
                for (int p = 0; p < 4; p++)
                    acc2[r][p] = fma2(xb[r], uv[p], acc2[r][p]);
        }
    }

    __syncthreads();                 // all xs0/xs2 reads done; reuse xs0 as g-tile
    #pragma unroll
    for (int r = 0; r < 4; r++) {
        #pragma unroll
        for (int p = 0; p < 4; p++) {
            float a0, a1v, c0, c1;
            unpack2(acc1[r][p], a0, a1v);
            unpack2(acc2[r][p], c0, c1);
            float th0 = 2.0f / (1.0f + __expf(-2.0f * a0)) - 1.0f;
            float th1 = 2.0f / (1.0f + __expf(-2.0f * a1v)) - 1.0f;
            float sg0 = 1.0f / (1.0f + __expf(-c0));
            float sg1 = 1.0f / (1.0f + __expf(-c1));
            xs0[(r0 + r) * 33 + co + 2 * p]     = th0 * sg0;
            xs0[(r0 + r) * 33 + co + 2 * p + 1] = th1 * sg1;
        }
    }
    __syncthreads();

    u64 hacc[4][4];
    u64 z = pack2(0.0f, 0.0f);
    #pragma unroll
    for (int r = 0; r < 4; r++)
        #pragma unroll
        for (int p = 0; p < 4; p++) hacc[r][p] = z;

    #pragma unroll 4
    for (int k = 0; k < 32; k++) {
        u64 gp[4];
        #pragma unroll
        for (int r = 0; r < 4; r++) {
            float gv = xs0[(r0 + r) * 33 + k];
            gp[r] = pack2(gv, gv);
        }
        ulonglong2 wlo = *(const ulonglong2*)&gws[k * 32 + co];
        ulonglong2 whi = *(const ulonglong2*)&gws[k * 32 + co + 4];
        u64 wv[4] = {wlo.x, wlo.y, whi.x, whi.y};
        #pragma unroll
        for (int r = 0; r < 4; r++)
            #pragma unroll
            for (int p = 0; p < 4; p++)
                hacc[r][p] = fma2(gp[r], wv[p], hacc[r][p]);
    }

    float* outp = g_hw + ((size_t)bt * N_NODES + n0) * C;
    #pragma unroll
    for (int r = 0; r < 4; r++) {
        int row = r0 + r;
        if (row < nrows) {
            ulonglong2 lo; lo.x = hacc[r][0]; lo.y = hacc[r][1];
            ulonglong2 hi; hi.x = hacc[r][2]; hi.y = hacc[r][3];
            *(ulonglong2*)&outp[row * 32 + co]     = lo;
            *(ulonglong2*)&outp[row * 32 + co + 4] = hi;
        }
    }
}

// ------------------------------------------------------------------
// Gather: warp per (bt, dst). lane = (half, channel-pair): half-warps process
// different edges (4 edges/iter/warp via 2 accs each), float2 loads, final
// shfl_xor(16) cross-half reduce. hw slice per bt (256KB) is L2-resident.
__global__ void k_gather(const float* __restrict__ gb, float* __restrict__ out) {
    int w = (blockIdx.x * blockDim.x + threadIdx.x) >> 5;
    if (w >= NBT * N_NODES) return;
    int lane = threadIdx.x & 31;
    int half = lane >> 4;           // 0 or 1
    int hl   = lane & 15;           // channel-pair index (ch = 2*hl, 2*hl+1)
    int bt  = w / N_NODES;
    int dst = w - bt * N_NODES;
    const float2* hb = (const float2*)(g_hw + (size_t)bt * (N_NODES * C));

    float2 acc0 = make_float2(0.0f, 0.0f);
    float2 acc1 = make_float2(0.0f, 0.0f);
    if (half == 0) {
        float2 bv = ((const float2*)gb)[hl];
        float idg = g_invdeg[dst];
        float2 sv = hb[dst * 16 + hl];
        acc0.x = bv.x + idg * sv.x;
        acc0.y = bv.y + idg * sv.y;
    }

    int s = g_off[dst], e = g_off[dst + 1];
    int i = s;
    for (; i + 3 < e; i += 4) {
        int ia = i + half * 2, ib = ia + 1;
        int   sa = g_src[ia]; float na = g_nrm[ia];
        int   sb = g_src[ib]; float nb = g_nrm[ib];
        float2 va = hb[sa * 16 + hl];
        float2 vb = hb[sb * 16 + hl];
        acc0.x += na * va.x; acc0.y += na * va.y;
        acc1.x += nb * vb.x; acc1.y += nb * vb.y;
    }
    for (; i + 1 < e; i += 2) {
        int ia = i + half;
        int sa = g_src[ia]; float na = g_nrm[ia];
        float2 va = hb[sa * 16 + hl];
        acc0.x += na * va.x; acc0.y += na * va.y;
    }
    if (i < e && half == 0) {
        int sa = g_src[i]; float na = g_nrm[i];
        float2 va = hb[sa * 16 + hl];
        acc0.x += na * va.x; acc0.y += na * va.y;
    }

    float rx = acc0.x + acc1.x;
    float ry = acc0.y + acc1.y;
    rx += __shfl_xor_sync(0xffffffffu, rx, 16);
    ry += __shfl_xor_sync(0xffffffffu, ry, 16);
    if (half == 0)
        ((float2*)out)[(size_t)w * 16 + hl] = make_float2(rx, ry);
}

// ------------------------------------------------------------------
extern "C" void kernel_launch(void* const* d_in, const int* in_sizes, int n_in,
                              void* d_out, int out_size) {
    const float* x  = (const float*)d_in[0];
    const void*  ei = d_in[1];                 // int64 OR int32 — detected per-block
    const float* ew = (const float*)d_in[2];
    const float* w1 = (const float*)d_in[3];
    const float* b1 = (const float*)d_in[4];
    const float* w2 = (const float*)d_in[5];
    const float* b2 = (const float*)d_in[6];
    const float* gw = (const float*)d_in[7];
    const float* gb = (const float*)d_in[8];
    float* out = (float*)d_out;

    k_deg  <<<(N_EDGES + 255) / 256, 256>>>(ei, ew);
    k_scan <<<1, 256>>>();
    k_fill <<<(N_EDGES + 255) / 256, 256>>>(ei, ew);

    int smem = (2 * 128 * 33 + 5 * 1024) * (int)sizeof(float);   // 54272 B
    cudaFuncSetAttribute(k_conv, cudaFuncAttributeMaxDynamicSharedMemorySize, smem);
    dim3 grid(16, NBT);
    k_conv<<<grid, 128, smem>>>(x, w1, b1, w2, b2, gw);

    int totw = NBT * N_NODES;                        // 256000 warps
    k_gather<<<(totw * 32 + 255) / 256, 256>>>(gb, out);
}